// round 1
// baseline (speedup 1.0000x reference)
#include <cuda_runtime.h>
#include <cuda_bf16.h>
#include <math.h>

// ---------------- problem constants ----------------
#define B_    8
#define S_    3072
#define H_    12
#define D_    128
#define E_    1536            // H_*D_
#define NB_   256             // S_/CHUNK
#define CHUNK_ 12
#define CTX_  24
#define MTOK_ (B_*S_)         // 24576

#define OUT_MAIN  ((size_t)MTOK_ * E_)                    // 37748736
#define ATTN_SZ   ((size_t)B_*H_*NB_*CHUNK_*CTX_)         // 7077888

// Q_SCALE = D^-0.5 / ln2 ; K_SCALE = ln(1+e)/ln2  (compiler folds)
#define QSCALE_BASE (0.088388347648318447f / 0.69314718055994531f)
#define KSCALE      (1.3132616875182228f  / 0.69314718055994531f)

// ---------------- scratch (device globals; no allocation allowed) ----------
__device__ float g_q[OUT_MAIN];
__device__ float g_k[OUT_MAIN];
__device__ float g_v[OUT_MAIN];
__device__ float g_o[OUT_MAIN];
__device__ float g_relk[CTX_ * E_];
__device__ float g_qdscale[D_];

// ---------------- per-dim query scale: Q_SCALE * softplus(pds[d]) ----------
__global__ void prep_scale_kernel(const float* __restrict__ pds, float* __restrict__ out)
{
    int d = threadIdx.x;
    if (d < D_) {
        float x = pds[d];
        // numerically stable softplus
        float sp = (x > 20.f) ? x : log1pf(expf(x));
        out[d] = QSCALE_BASE * sp;
    }
}

// ---------------- NT GEMM: C[M,N] = A[M,K] * B[N,K]^T  (both K-contiguous) --
// 128x128 block tile, BK=16, 256 threads, 8x8 per-thread microtile.
// mode 0: none; mode 1: *= colscale[c%128]; mode 2: *= cscale
__global__ void __launch_bounds__(256, 2)
gemm_nt_kernel(const float* __restrict__ A, const float* __restrict__ Bm,
               float* __restrict__ C, int M, int N, int K,
               int mode, const float* __restrict__ colscale, float cscale)
{
    __shared__ float As[16][128];
    __shared__ float Bs[16][128];

    const int bm = blockIdx.y * 128;
    const int bn = blockIdx.x * 128;
    const int t  = threadIdx.x;

    const int lr = t >> 2;          // 0..63 (load row)
    const int lc = (t & 3) << 2;    // 0,4,8,12 (load col group of 4)
    const int tx = t & 15;          // 0..15
    const int ty = t >> 4;          // 0..15

    float acc[8][8];
#pragma unroll
    for (int i = 0; i < 8; i++)
#pragma unroll
        for (int j = 0; j < 8; j++) acc[i][j] = 0.f;

    for (int kt = 0; kt < K; kt += 16) {
        float4 a0 = make_float4(0.f,0.f,0.f,0.f);
        float4 a1 = make_float4(0.f,0.f,0.f,0.f);
        const int r0 = bm + lr, r1 = bm + lr + 64;
        if (r0 < M) a0 = *(const float4*)(A + (size_t)r0 * K + kt + lc);
        if (r1 < M) a1 = *(const float4*)(A + (size_t)r1 * K + kt + lc);
        const float4 b0 = *(const float4*)(Bm + (size_t)(bn + lr)      * K + kt + lc);
        const float4 b1 = *(const float4*)(Bm + (size_t)(bn + lr + 64) * K + kt + lc);

        __syncthreads();
        As[lc+0][lr]    = a0.x; As[lc+1][lr]    = a0.y; As[lc+2][lr]    = a0.z; As[lc+3][lr]    = a0.w;
        As[lc+0][lr+64] = a1.x; As[lc+1][lr+64] = a1.y; As[lc+2][lr+64] = a1.z; As[lc+3][lr+64] = a1.w;
        Bs[lc+0][lr]    = b0.x; Bs[lc+1][lr]    = b0.y; Bs[lc+2][lr]    = b0.z; Bs[lc+3][lr]    = b0.w;
        Bs[lc+0][lr+64] = b1.x; Bs[lc+1][lr+64] = b1.y; Bs[lc+2][lr+64] = b1.z; Bs[lc+3][lr+64] = b1.w;
        __syncthreads();

#pragma unroll
        for (int kk = 0; kk < 16; kk++) {
            float a[8], b[8];
            *(float4*)(a)     = *(const float4*)&As[kk][ty * 8];
            *(float4*)(a + 4) = *(const float4*)&As[kk][ty * 8 + 4];
            *(float4*)(b)     = *(const float4*)&Bs[kk][tx * 8];
            *(float4*)(b + 4) = *(const float4*)&Bs[kk][tx * 8 + 4];
#pragma unroll
            for (int i = 0; i < 8; i++)
#pragma unroll
                for (int j = 0; j < 8; j++)
                    acc[i][j] = fmaf(a[i], b[j], acc[i][j]);
        }
    }

#pragma unroll
    for (int i = 0; i < 8; i++) {
        const int r = bm + ty * 8 + i;
        if (r >= M) continue;
#pragma unroll
        for (int j = 0; j < 8; j++) {
            const int c = bn + tx * 8 + j;
            float val = acc[i][j];
            if (mode == 1)      val *= colscale[c & (D_ - 1)];
            else if (mode == 2) val *= cscale;
            C[(size_t)r * N + c] = val;
        }
    }
}

// ---------------- chunked local attention -----------------------------------
// grid: (nb=256, H=12, B=8), block: 384 threads
__global__ void __launch_bounds__(384)
attn_kernel(const float* __restrict__ q, const float* __restrict__ k,
            const float* __restrict__ v, const float* __restrict__ relk,
            float* __restrict__ o, float* __restrict__ attn_out)
{
    __shared__ float sq[CHUNK_][129];
    __shared__ float sk[CTX_][129];
    __shared__ float sv[CTX_][129];
    __shared__ float sr[CTX_][129];
    __shared__ float sac[CHUNK_][CTX_];
    __shared__ float sbd[CHUNK_][CTX_];
    __shared__ float sw[CHUNK_][25];

    const int n = blockIdx.x, h = blockIdx.y, b = blockIdx.z;
    const int t = threadIdx.x;

    // load q rows for this chunk
    for (int i = t; i < CHUNK_ * D_; i += 384) {
        const int c = i >> 7, d = i & 127;
        const int s = n * CHUNK_ + c;
        sq[c][d] = q[((size_t)(b * S_ + s)) * E_ + h * D_ + d];
    }
    // load k/v context window (left pad = 12) and rel_k
    for (int i = t; i < CTX_ * D_; i += 384) {
        const int j = i >> 7, d = i & 127;
        const int s = n * CHUNK_ - 12 + j;
        float kv = 0.f, vv = 0.f;
        if (s >= 0 && s < S_) {
            const size_t base = ((size_t)(b * S_ + s)) * E_ + h * D_ + d;
            kv = k[base]; vv = v[base];
        }
        sk[j][d] = kv;
        sv[j][d] = vv;
        sr[j][d] = relk[(size_t)j * E_ + h * D_ + d];
    }
    __syncthreads();

    // content (ac) and position (bd) logits: 12x24 dots of length 128
    for (int i = t; i < CHUNK_ * CTX_; i += 384) {
        const int c = i / CTX_, j = i % CTX_;
        float a = 0.f, bb = 0.f;
#pragma unroll 8
        for (int d = 0; d < D_; d++) {
            const float qq = sq[c][d];
            a  = fmaf(qq, sk[j][d], a);
            bb = fmaf(qq, sr[j][d], bb);
        }
        sac[c][j] = a;
        sbd[c][j] = bb;
    }
    __syncthreads();

    // rel-shift + softcap
    for (int i = t; i < CHUNK_ * CTX_; i += 384) {
        const int c = i / CTX_, j = i % CTX_;
        const int idx = c * CTX_ + j;
        const int r = idx / (CTX_ + 1);
        const int p = idx % (CTX_ + 1);
        const float bd = (p < CTX_) ? sbd[r][p] : 0.f;
        float l = sac[c][j] + bd;
        l = 50.f * tanhf(l * 0.02f);
        sw[c][j] = l;
    }
    __syncthreads();

    // softmax over ctx (rows are tiny: 24)
    if (t < CHUNK_) {
        const int c = t;
        float m = -1e30f;
        for (int j = 0; j < CTX_; j++) m = fmaxf(m, sw[c][j]);
        float sum = 0.f;
        for (int j = 0; j < CTX_; j++) { const float e = expf(sw[c][j] - m); sum += e; sw[c][j] = e; }
        const float inv = 1.f / sum;
        for (int j = 0; j < CTX_; j++) sw[c][j] *= inv;
    }
    __syncthreads();

    if (attn_out) {
        for (int i = t; i < CHUNK_ * CTX_; i += 384) {
            const int c = i / CTX_, j = i % CTX_;
            attn_out[((((size_t)b * H_ + h) * NB_ + n) * CHUNK_ + c) * CTX_ + j] = sw[c][j];
        }
    }

    // out[c][d] = sum_j w[c][j] * v[j][d]
    for (int i = t; i < CHUNK_ * D_; i += 384) {
        const int c = i >> 7, d = i & 127;
        float acc = 0.f;
#pragma unroll
        for (int j = 0; j < CTX_; j++) acc = fmaf(sw[c][j], sv[j][d], acc);
        o[((size_t)(b * S_ + n * CHUNK_ + c)) * E_ + h * D_ + d] = acc;
    }
}

// ---------------- launch -----------------------------------------------------
extern "C" void kernel_launch(void* const* d_in, const int* in_sizes, int n_in,
                              void* d_out, int out_size)
{
    const float* hs   = (const float*)d_in[0];  // hidden_states [B,S,E]
    const float* pe   = (const float*)d_in[1];  // position_embeddings [24,E]
    const float* w_q  = (const float*)d_in[2];
    const float* w_k  = (const float*)d_in[3];
    const float* w_v  = (const float*)d_in[4];
    const float* w_p  = (const float*)d_in[5];
    const float* w_r  = (const float*)d_in[6];
    const float* pds  = (const float*)d_in[7];  // per_dim_scale [128]
    float* out = (float*)d_out;

    float *q, *k, *v, *o, *rk, *qs;
    cudaGetSymbolAddress((void**)&q,  g_q);
    cudaGetSymbolAddress((void**)&k,  g_k);
    cudaGetSymbolAddress((void**)&v,  g_v);
    cudaGetSymbolAddress((void**)&o,  g_o);
    cudaGetSymbolAddress((void**)&rk, g_relk);
    cudaGetSymbolAddress((void**)&qs, g_qdscale);

    prep_scale_kernel<<<1, 128>>>(pds, qs);

    const dim3 gBig(E_ / 128, MTOK_ / 128);     // (12, 192)
    gemm_nt_kernel<<<gBig, 256>>>(hs, w_q, q, MTOK_, E_, E_, 1, qs, 1.f);
    gemm_nt_kernel<<<gBig, 256>>>(hs, w_k, k, MTOK_, E_, E_, 2, nullptr, KSCALE);
    gemm_nt_kernel<<<gBig, 256>>>(hs, w_v, v, MTOK_, E_, E_, 0, nullptr, 1.f);
    gemm_nt_kernel<<<dim3(E_ / 128, 1), 256>>>(pe, w_r, rk, CTX_, E_, E_, 0, nullptr, 1.f);

    float* attn = ((size_t)out_size >= OUT_MAIN + ATTN_SZ) ? (out + OUT_MAIN) : nullptr;
    attn_kernel<<<dim3(NB_, H_, B_), 384>>>(q, k, v, rk, o, attn);

    gemm_nt_kernel<<<gBig, 256>>>(o, w_p, out, MTOK_, E_, E_, 0, nullptr, 1.f);
}

// round 3
// speedup vs baseline: 1.9941x; 1.9941x over previous
#include <cuda_runtime.h>
#include <cuda_bf16.h>
#include <stdint.h>
#include <math.h>

// ---------------- problem constants ----------------
#define B_    8
#define S_    3072
#define H_    12
#define D_    128
#define E_    1536
#define NB_   256
#define CHUNK_ 12
#define CTX_  24
#define MTOK_ (B_*S_)         // 24576

#define OUT_MAIN  ((size_t)MTOK_ * E_)
#define ATTN_SZ   ((size_t)B_*H_*NB_*CHUNK_*CTX_)

#define QSCALE_BASE (0.088388347648318447f / 0.69314718055994531f)
#define KSCALE      (1.3132616875182228f  / 0.69314718055994531f)

// ---------------- scratch ----------------
__device__ float g_q[OUT_MAIN];
__device__ float g_k[OUT_MAIN];
__device__ float g_v[OUT_MAIN];
__device__ float g_o[OUT_MAIN];
__device__ float g_relk[CTX_ * E_];
__device__ float g_qdscale[D_];

__global__ void prep_scale_kernel(const float* __restrict__ pds, float* __restrict__ out)
{
    int d = threadIdx.x;
    if (d < D_) {
        float x = pds[d];
        float sp = (x > 20.f) ? x : log1pf(expf(x));
        out[d] = QSCALE_BASE * sp;
    }
}

// ============================================================================
// TF32 tensor-core NT GEMM: C[M,N] = A[M,K] * B[N,K]^T
// 128x128 CTA tile, BK=32, 256 threads (8 warps in 2x4), warp tile 64x32,
// m16n8k8 mma. SPLIT=true -> tf32x3 (near-fp32 accuracy).
// ============================================================================
#define LDA_   36                   // 32 data + 4 pad floats (conflict-free)
#define ABUF_  (128*LDA_)           // floats per buffer per matrix
#define SMEM_BYTES_ (2*2*ABUF_*4)   // 73728

__device__ __forceinline__ unsigned f2tf(float x){
    unsigned u; asm("cvt.rna.tf32.f32 %0, %1;" : "=r"(u) : "f"(x)); return u;
}
__device__ __forceinline__ unsigned cvt_frag(float x, bool lo){
    unsigned h = f2tf(x);
    if (!lo) return h;
    return f2tf(x - __uint_as_float(h));
}
__device__ __forceinline__ void mma_tf32(float c[4], unsigned a0, unsigned a1,
                                         unsigned a2, unsigned a3,
                                         unsigned b0, unsigned b1){
    asm volatile(
        "mma.sync.aligned.m16n8k8.row.col.f32.tf32.tf32.f32 "
        "{%0,%1,%2,%3}, {%4,%5,%6,%7}, {%8,%9}, {%0,%1,%2,%3};"
        : "+f"(c[0]), "+f"(c[1]), "+f"(c[2]), "+f"(c[3])
        : "r"(a0), "r"(a1), "r"(a2), "r"(a3), "r"(b0), "r"(b1));
}
__device__ __forceinline__ void cpasync16(unsigned smem_addr, const void* gptr, int szbytes){
    asm volatile("cp.async.cg.shared.global [%0], [%1], 16, %2;"
                 :: "r"(smem_addr), "l"(gptr), "r"(szbytes) : "memory");
}

template<bool SPLIT>
__global__ void __launch_bounds__(256, 2)
gemm_tc(const float* __restrict__ A, const float* __restrict__ Bm,
        float* __restrict__ C, int M, int N, int K,
        int mode, const float* __restrict__ colscale, float cscale)
{
    extern __shared__ float sm[];
    float* As = sm;                 // [2][128][LDA_]
    float* Bs = sm + 2*ABUF_;

    const int bm = blockIdx.y * 128;
    const int bn = blockIdx.x * 128;
    const int tid  = threadIdx.x;
    const int lane = tid & 31;
    const int warp = tid >> 5;
    const int wm = warp >> 2;       // 0..1
    const int wn = warp & 3;        // 0..3
    const int lr = lane >> 2;       // 0..7
    const int lc = lane & 3;        // 0..3

    float acc[4][4][4];
#pragma unroll
    for (int i = 0; i < 4; i++)
#pragma unroll
        for (int j = 0; j < 4; j++)
#pragma unroll
            for (int r = 0; r < 4; r++) acc[i][j][r] = 0.f;

    const unsigned sA = (unsigned)__cvta_generic_to_shared(As);
    const unsigned sB = (unsigned)__cvta_generic_to_shared(Bs);
    const int NK = K >> 5;

    // --- async tile load: 4 chunks of 16B per thread per matrix ---
    auto issue = [&](int it, int buf){
        const int kt = it << 5;
#pragma unroll
        for (int i = 0; i < 4; i++) {
            const int id  = i * 256 + tid;
            const int row = id >> 3;
            const int ch  = id & 7;
            const unsigned soff = (unsigned)((buf * ABUF_ + row * LDA_ + ch * 4) * 4);
            // A (row-guarded for the M=24 rel GEMM)
            const int gr  = bm + row;
            const int sz  = (gr < M) ? 16 : 0;
            const int grc = (gr < M) ? gr : 0;
            cpasync16(sA + soff, A + (size_t)grc * K + kt + ch * 4, sz);
            // B (N,K always full tiles)
            cpasync16(sB + soff, Bm + (size_t)(bn + row) * K + kt + ch * 4, 16);
        }
        asm volatile("cp.async.commit_group;" ::: "memory");
    };

    issue(0, 0);
    int buf = 0;

    for (int it = 0; it < NK; it++) {
        if (it + 1 < NK) {
            issue(it + 1, buf ^ 1);
            asm volatile("cp.async.wait_group 1;" ::: "memory");
        } else {
            asm volatile("cp.async.wait_group 0;" ::: "memory");
        }
        __syncthreads();

        const float* Ab = As + buf * ABUF_;
        const float* Bb = Bs + buf * ABUF_;

#pragma unroll
        for (int k0 = 0; k0 < 32; k0 += 8) {
            const int NPASS = SPLIT ? 3 : 1;
#pragma unroll 1
            for (int p = 0; p < NPASS; p++) {
                const bool alo = (p == 1);
                const bool blo = (p == 2);
                unsigned af[4][4];
#pragma unroll
                for (int mt = 0; mt < 4; mt++) {
                    const int r = wm * 64 + mt * 16 + lr;
                    const int c = k0 + lc;
                    af[mt][0] = cvt_frag(Ab[r * LDA_ + c],           alo);
                    af[mt][1] = cvt_frag(Ab[(r + 8) * LDA_ + c],     alo);
                    af[mt][2] = cvt_frag(Ab[r * LDA_ + c + 4],       alo);
                    af[mt][3] = cvt_frag(Ab[(r + 8) * LDA_ + c + 4], alo);
                }
                unsigned bf[4][2];
#pragma unroll
                for (int nt = 0; nt < 4; nt++) {
                    const int r = wn * 32 + nt * 8 + lr;
                    const int c = k0 + lc;
                    bf[nt][0] = cvt_frag(Bb[r * LDA_ + c],     blo);
                    bf[nt][1] = cvt_frag(Bb[r * LDA_ + c + 4], blo);
                }
#pragma unroll
                for (int mt = 0; mt < 4; mt++)
#pragma unroll
                    for (int nt = 0; nt < 4; nt++)
                        mma_tf32(acc[mt][nt], af[mt][0], af[mt][1], af[mt][2], af[mt][3],
                                 bf[nt][0], bf[nt][1]);
            }
        }
        __syncthreads();
        buf ^= 1;
    }

    // --- epilogue ---
#pragma unroll
    for (int mt = 0; mt < 4; mt++) {
#pragma unroll
        for (int nt = 0; nt < 4; nt++) {
            const int r0 = bm + wm * 64 + mt * 16 + lr;
            const int c0 = bn + wn * 32 + nt * 8 + 2 * lc;
            float v0 = acc[mt][nt][0], v1 = acc[mt][nt][1];
            float v2 = acc[mt][nt][2], v3 = acc[mt][nt][3];
            if (mode == 1) {
                const float s0 = colscale[c0 & (D_-1)], s1 = colscale[(c0+1) & (D_-1)];
                v0 *= s0; v1 *= s1; v2 *= s0; v3 *= s1;
            } else if (mode == 2) {
                v0 *= cscale; v1 *= cscale; v2 *= cscale; v3 *= cscale;
            }
            if (r0 < M)     *(float2*)(C + (size_t)r0      * N + c0) = make_float2(v0, v1);
            if (r0 + 8 < M) *(float2*)(C + (size_t)(r0+8)  * N + c0) = make_float2(v2, v3);
        }
    }
}

// ---------------- chunked local attention -----------------------------------
__global__ void __launch_bounds__(384)
attn_kernel(const float* __restrict__ q, const float* __restrict__ k,
            const float* __restrict__ v, const float* __restrict__ relk,
            float* __restrict__ o, float* __restrict__ attn_out)
{
    __shared__ float sq[CHUNK_][129];
    __shared__ float sk[CTX_][129];
    __shared__ float sv[CTX_][129];
    __shared__ float sr[CTX_][129];
    __shared__ float sac[CHUNK_][CTX_];
    __shared__ float sbd[CHUNK_][CTX_];
    __shared__ float sw[CHUNK_][25];

    const int n = blockIdx.x, h = blockIdx.y, b = blockIdx.z;
    const int t = threadIdx.x;

    for (int i = t; i < CHUNK_ * D_; i += 384) {
        const int c = i >> 7, d = i & 127;
        const int s = n * CHUNK_ + c;
        sq[c][d] = q[((size_t)(b * S_ + s)) * E_ + h * D_ + d];
    }
    for (int i = t; i < CTX_ * D_; i += 384) {
        const int j = i >> 7, d = i & 127;
        const int s = n * CHUNK_ - 12 + j;
        float kv = 0.f, vv = 0.f;
        if (s >= 0 && s < S_) {
            const size_t base = ((size_t)(b * S_ + s)) * E_ + h * D_ + d;
            kv = k[base]; vv = v[base];
        }
        sk[j][d] = kv;
        sv[j][d] = vv;
        sr[j][d] = relk[(size_t)j * E_ + h * D_ + d];
    }
    __syncthreads();

    for (int i = t; i < CHUNK_ * CTX_; i += 384) {
        const int c = i / CTX_, j = i % CTX_;
        float a = 0.f, bb = 0.f;
#pragma unroll 8
        for (int d = 0; d < D_; d++) {
            const float qq = sq[c][d];
            a  = fmaf(qq, sk[j][d], a);
            bb = fmaf(qq, sr[j][d], bb);
        }
        sac[c][j] = a;
        sbd[c][j] = bb;
    }
    __syncthreads();

    for (int i = t; i < CHUNK_ * CTX_; i += 384) {
        const int c = i / CTX_, j = i % CTX_;
        const int idx = c * CTX_ + j;
        const int r = idx / (CTX_ + 1);
        const int p = idx % (CTX_ + 1);
        const float bd = (p < CTX_) ? sbd[r][p] : 0.f;
        float l = sac[c][j] + bd;
        l = 50.f * tanhf(l * 0.02f);
        sw[c][j] = l;
    }
    __syncthreads();

    if (t < CHUNK_) {
        const int c = t;
        float m = -1e30f;
        for (int j = 0; j < CTX_; j++) m = fmaxf(m, sw[c][j]);
        float sum = 0.f;
        for (int j = 0; j < CTX_; j++) { const float e = expf(sw[c][j] - m); sum += e; sw[c][j] = e; }
        const float inv = 1.f / sum;
        for (int j = 0; j < CTX_; j++) sw[c][j] *= inv;
    }
    __syncthreads();

    if (attn_out) {
        for (int i = t; i < CHUNK_ * CTX_; i += 384) {
            const int c = i / CTX_, j = i % CTX_;
            attn_out[((((size_t)b * H_ + h) * NB_ + n) * CHUNK_ + c) * CTX_ + j] = sw[c][j];
        }
    }

    for (int i = t; i < CHUNK_ * D_; i += 384) {
        const int c = i >> 7, d = i & 127;
        float acc = 0.f;
#pragma unroll
        for (int j = 0; j < CTX_; j++) acc = fmaf(sw[c][j], sv[j][d], acc);
        o[((size_t)(b * S_ + n * CHUNK_ + c)) * E_ + h * D_ + d] = acc;
    }
}

// ---------------- launch -----------------------------------------------------
extern "C" void kernel_launch(void* const* d_in, const int* in_sizes, int n_in,
                              void* d_out, int out_size)
{
    const float* hs   = (const float*)d_in[0];
    const float* pe   = (const float*)d_in[1];
    const float* w_q  = (const float*)d_in[2];
    const float* w_k  = (const float*)d_in[3];
    const float* w_v  = (const float*)d_in[4];
    const float* w_p  = (const float*)d_in[5];
    const float* w_r  = (const float*)d_in[6];
    const float* pds  = (const float*)d_in[7];
    float* out = (float*)d_out;

    float *q, *k, *v, *o, *rk, *qs;
    cudaGetSymbolAddress((void**)&q,  g_q);
    cudaGetSymbolAddress((void**)&k,  g_k);
    cudaGetSymbolAddress((void**)&v,  g_v);
    cudaGetSymbolAddress((void**)&o,  g_o);
    cudaGetSymbolAddress((void**)&rk, g_relk);
    cudaGetSymbolAddress((void**)&qs, g_qdscale);

    cudaFuncSetAttribute(gemm_tc<true>,  cudaFuncAttributeMaxDynamicSharedMemorySize, SMEM_BYTES_);
    cudaFuncSetAttribute(gemm_tc<false>, cudaFuncAttributeMaxDynamicSharedMemorySize, SMEM_BYTES_);

    prep_scale_kernel<<<1, 128>>>(pds, qs);

    const dim3 gBig(E_ / 128, MTOK_ / 128);
    // q, k feed attention logits -> tf32x3; rel also (cheap). v plain tf32.
    gemm_tc<true ><<<gBig, 256, SMEM_BYTES_>>>(hs, w_q, q, MTOK_, E_, E_, 1, qs, 1.f);
    gemm_tc<true ><<<gBig, 256, SMEM_BYTES_>>>(hs, w_k, k, MTOK_, E_, E_, 2, nullptr, KSCALE);
    gemm_tc<false><<<gBig, 256, SMEM_BYTES_>>>(hs, w_v, v, MTOK_, E_, E_, 0, nullptr, 1.f);
    gemm_tc<true ><<<dim3(E_ / 128, 1), 256, SMEM_BYTES_>>>(pe, w_r, rk, CTX_, E_, E_, 0, nullptr, 1.f);

    float* attn = ((size_t)out_size >= OUT_MAIN + ATTN_SZ) ? (out + OUT_MAIN) : nullptr;
    attn_kernel<<<dim3(NB_, H_, B_), 384>>>(q, k, v, rk, o, attn);

    gemm_tc<true ><<<gBig, 256, SMEM_BYTES_>>>(o, w_p, out, MTOK_, E_, E_, 0, nullptr, 1.f);
}

// round 5
// speedup vs baseline: 2.8547x; 1.4316x over previous
#include <cuda_runtime.h>
#include <cuda_bf16.h>
#include <stdint.h>
#include <math.h>

// ---------------- problem constants ----------------
#define B_    8
#define S_    3072
#define H_    12
#define D_    128
#define E_    1536
#define NB_   256
#define CHUNK_ 12
#define CTX_  24
#define MTOK_ (B_*S_)         // 24576

#define OUT_MAIN  ((size_t)MTOK_ * E_)
#define ATTN_SZ   ((size_t)B_*H_*NB_*CHUNK_*CTX_)
#define WELEM_    (E_*E_)

#define QSCALE_BASE (0.088388347648318447f / 0.69314718055994531f)
#define KSCALE      (1.3132616875182228f  / 0.69314718055994531f)

// ---------------- scratch (device globals) ----------------
__device__ float g_q[OUT_MAIN];
__device__ float g_k[OUT_MAIN];
__device__ float g_v[OUT_MAIN];
__device__ float g_o[OUT_MAIN];
__device__ float g_relk[CTX_ * E_];
__device__ float g_qdscale[D_];

__device__ __nv_bfloat16 g_hs_hi[OUT_MAIN];
__device__ __nv_bfloat16 g_hs_lo[OUT_MAIN];
__device__ __nv_bfloat16 g_oc_hi[OUT_MAIN];
__device__ __nv_bfloat16 g_oc_lo[OUT_MAIN];
__device__ __nv_bfloat16 g_w_hi[5][WELEM_];
__device__ __nv_bfloat16 g_w_lo[5][WELEM_];
__device__ __nv_bfloat16 g_pe_hi[128 * E_];
__device__ __nv_bfloat16 g_pe_lo[128 * E_];

// ---------------- helpers ----------------
__device__ __forceinline__ void mma_bf16(float c[4], unsigned a0, unsigned a1,
                                         unsigned a2, unsigned a3,
                                         unsigned b0, unsigned b1){
    asm volatile(
        "mma.sync.aligned.m16n8k16.row.col.f32.bf16.bf16.f32 "
        "{%0,%1,%2,%3}, {%4,%5,%6,%7}, {%8,%9}, {%0,%1,%2,%3};"
        : "+f"(c[0]), "+f"(c[1]), "+f"(c[2]), "+f"(c[3])
        : "r"(a0), "r"(a1), "r"(a2), "r"(a3), "r"(b0), "r"(b1));
}
__device__ __forceinline__ void cpasync16(unsigned saddr, const void* gptr){
    asm volatile("cp.async.cg.shared.global [%0], [%1], 16;"
                 :: "r"(saddr), "l"(gptr) : "memory");
}

// ---------------- fp32 -> bf16 hi/lo split ----------------
__global__ void split_kernel(const float* __restrict__ src,
                             __nv_bfloat16* __restrict__ hi,
                             __nv_bfloat16* __restrict__ lo,
                             int nvalid4, int ntotal4)
{
    int i = blockIdx.x * 256 + threadIdx.x;
    if (i >= ntotal4) return;
    float4 x = (i < nvalid4) ? ((const float4*)src)[i] : make_float4(0.f,0.f,0.f,0.f);
    __nv_bfloat16 h0 = __float2bfloat16_rn(x.x);
    __nv_bfloat16 h1 = __float2bfloat16_rn(x.y);
    __nv_bfloat16 h2 = __float2bfloat16_rn(x.z);
    __nv_bfloat16 h3 = __float2bfloat16_rn(x.w);
    __nv_bfloat162* hp = (__nv_bfloat162*)(hi + (size_t)i * 4);
    hp[0] = __nv_bfloat162(h0, h1);
    hp[1] = __nv_bfloat162(h2, h3);
    __nv_bfloat162* lp = (__nv_bfloat162*)(lo + (size_t)i * 4);
    lp[0] = __nv_bfloat162(__float2bfloat16_rn(x.x - __bfloat162float(h0)),
                           __float2bfloat16_rn(x.y - __bfloat162float(h1)));
    lp[1] = __nv_bfloat162(__float2bfloat16_rn(x.z - __bfloat162float(h2)),
                           __float2bfloat16_rn(x.w - __bfloat162float(h3)));
}

__global__ void prep_scale_kernel(const float* __restrict__ pds, float* __restrict__ out)
{
    int d = threadIdx.x;
    if (d < D_) {
        float x = pds[d];
        float sp = (x > 20.f) ? x : log1pf(expf(x));
        out[d] = QSCALE_BASE * sp;
    }
}

// ============================================================================
// bf16x3 tensor-core NT GEMM: C[M,N] = A[M,K]*B[N,K]^T (fp32-accurate).
// 128x128 CTA tile, BK=32, 256 threads (8 warps 2x4), warp tile 64x32,
// m16n8k16 bf16 mma, 3 passes: Ah*Bh + Al*Bh + Ah*Bl.
// A rows beyond M must be pre-zeroed in the hi/lo buffers (done by split).
// ============================================================================
#define BKH_   32                    // K halves per tile
#define LDAH_  40                    // 32 + 8 pad halves -> 80B pitch, conflict-free
#define TILEB_ (128*LDAH_*2)         // 10240 bytes per matrix tile
#define BUFB_  (4*TILEB_)            // Ah, Al, Bh, Bl
#define SMEM_GEMM_ (2*BUFB_)         // 81920

__global__ void __launch_bounds__(256, 2)
gemm_bf16x3(const __nv_bfloat16* __restrict__ Ahi, const __nv_bfloat16* __restrict__ Alo,
            const __nv_bfloat16* __restrict__ Bhi, const __nv_bfloat16* __restrict__ Blo,
            float* __restrict__ C, int M, int N, int K,
            int mode, const float* __restrict__ colscale, float cscale)
{
    extern __shared__ char smem[];
    const unsigned sb = (unsigned)__cvta_generic_to_shared(smem);

    const int bm = blockIdx.y * 128;
    const int bn = blockIdx.x * 128;
    const int tid  = threadIdx.x;
    const int lane = tid & 31;
    const int warp = tid >> 5;
    const int wm = warp >> 2;       // 0..1
    const int wn = warp & 3;        // 0..3
    const int lr = lane >> 2;       // 0..7
    const int lc = lane & 3;        // 0..3

    float acc[4][4][4];
#pragma unroll
    for (int i = 0; i < 4; i++)
#pragma unroll
        for (int j = 0; j < 4; j++)
#pragma unroll
            for (int r = 0; r < 4; r++) acc[i][j][r] = 0.f;

    const int NK = K / BKH_;        // 48

    // loader: tt selects matrix (Ah,Al,Bh,Bl); 8 x 16B chunks per thread
    const int tt  = tid >> 6;
    const int loc = tid & 63;
    const __nv_bfloat16* gbase =
        (tt == 0) ? Ahi : (tt == 1) ? Alo : (tt == 2) ? Bhi : Blo;
    const int rbase = (tt < 2) ? bm : bn;

    auto issue_loads = [&](int it, int buf){
        const int kt = it * BKH_;
#pragma unroll
        for (int i = 0; i < 8; i++) {
            const int cid = loc * 8 + i;       // 0..511
            const int row = cid >> 2;          // 0..127
            const int ch  = cid & 3;           // 0..3 (16B = 8 halves)
            const unsigned soff = (unsigned)(buf * BUFB_ + tt * TILEB_ + row * (LDAH_*2) + ch * 16);
            cpasync16(sb + soff, gbase + (size_t)(rbase + row) * K + kt + ch * 8);
        }
        asm volatile("cp.async.commit_group;" ::: "memory");
    };

    issue_loads(0, 0);
    int buf = 0;

    for (int it = 0; it < NK; it++) {
        if (it + 1 < NK) {
            issue_loads(it + 1, buf ^ 1);
            asm volatile("cp.async.wait_group 1;" ::: "memory");
        } else {
            asm volatile("cp.async.wait_group 0;" ::: "memory");
        }
        __syncthreads();

        const char* base = smem + buf * BUFB_;
        const char* Ah = base;
        const char* Al = base + TILEB_;
        const char* Bh = base + 2 * TILEB_;
        const char* Bl = base + 3 * TILEB_;

#pragma unroll
        for (int k0 = 0; k0 < BKH_; k0 += 16) {
            // fragment smem offsets (halves -> bytes)
            // A frag reg i: rows wm*64+mt*16+lr (+8), cols k0+2*lc (+8)
            unsigned ah[4][4], bh[4][2];
#pragma unroll
            for (int mt = 0; mt < 4; mt++) {
                const int r = wm * 64 + mt * 16 + lr;
                const int c = k0 + 2 * lc;
                ah[mt][0] = *(const unsigned*)(Ah + (r     * LDAH_ + c    ) * 2);
                ah[mt][1] = *(const unsigned*)(Ah + ((r+8) * LDAH_ + c    ) * 2);
                ah[mt][2] = *(const unsigned*)(Ah + (r     * LDAH_ + c + 8) * 2);
                ah[mt][3] = *(const unsigned*)(Ah + ((r+8) * LDAH_ + c + 8) * 2);
            }
#pragma unroll
            for (int nt = 0; nt < 4; nt++) {
                const int r = wn * 32 + nt * 8 + lr;
                const int c = k0 + 2 * lc;
                bh[nt][0] = *(const unsigned*)(Bh + (r * LDAH_ + c    ) * 2);
                bh[nt][1] = *(const unsigned*)(Bh + (r * LDAH_ + c + 8) * 2);
            }
#pragma unroll
            for (int mt = 0; mt < 4; mt++)
#pragma unroll
                for (int nt = 0; nt < 4; nt++)
                    mma_bf16(acc[mt][nt], ah[mt][0], ah[mt][1], ah[mt][2], ah[mt][3],
                             bh[nt][0], bh[nt][1]);

            // pass 2: Al * Bh
            unsigned al[4][4];
#pragma unroll
            for (int mt = 0; mt < 4; mt++) {
                const int r = wm * 64 + mt * 16 + lr;
                const int c = k0 + 2 * lc;
                al[mt][0] = *(const unsigned*)(Al + (r     * LDAH_ + c    ) * 2);
                al[mt][1] = *(const unsigned*)(Al + ((r+8) * LDAH_ + c    ) * 2);
                al[mt][2] = *(const unsigned*)(Al + (r     * LDAH_ + c + 8) * 2);
                al[mt][3] = *(const unsigned*)(Al + ((r+8) * LDAH_ + c + 8) * 2);
            }
#pragma unroll
            for (int mt = 0; mt < 4; mt++)
#pragma unroll
                for (int nt = 0; nt < 4; nt++)
                    mma_bf16(acc[mt][nt], al[mt][0], al[mt][1], al[mt][2], al[mt][3],
                             bh[nt][0], bh[nt][1]);

            // pass 3: Ah * Bl
            unsigned bl[4][2];
#pragma unroll
            for (int nt = 0; nt < 4; nt++) {
                const int r = wn * 32 + nt * 8 + lr;
                const int c = k0 + 2 * lc;
                bl[nt][0] = *(const unsigned*)(Bl + (r * LDAH_ + c    ) * 2);
                bl[nt][1] = *(const unsigned*)(Bl + (r * LDAH_ + c + 8) * 2);
            }
#pragma unroll
            for (int mt = 0; mt < 4; mt++)
#pragma unroll
                for (int nt = 0; nt < 4; nt++)
                    mma_bf16(acc[mt][nt], ah[mt][0], ah[mt][1], ah[mt][2], ah[mt][3],
                             bl[nt][0], bl[nt][1]);
        }
        __syncthreads();
        buf ^= 1;
    }

    // --- epilogue ---
#pragma unroll
    for (int mt = 0; mt < 4; mt++) {
#pragma unroll
        for (int nt = 0; nt < 4; nt++) {
            const int r0 = bm + wm * 64 + mt * 16 + lr;
            const int c0 = bn + wn * 32 + nt * 8 + 2 * lc;
            float v0 = acc[mt][nt][0], v1 = acc[mt][nt][1];
            float v2 = acc[mt][nt][2], v3 = acc[mt][nt][3];
            if (mode == 1) {
                const float s0 = colscale[c0 & (D_-1)], s1 = colscale[(c0+1) & (D_-1)];
                v0 *= s0; v1 *= s1; v2 *= s0; v3 *= s1;
            } else if (mode == 2) {
                v0 *= cscale; v1 *= cscale; v2 *= cscale; v3 *= cscale;
            }
            if (r0 < M)     *(float2*)(C + (size_t)r0      * N + c0) = make_float2(v0, v1);
            if (r0 + 8 < M) *(float2*)(C + (size_t)(r0+8)  * N + c0) = make_float2(v2, v3);
        }
    }
}

// ---------------- chunked local attention -----------------------------------
__global__ void __launch_bounds__(384)
attn_kernel(const float* __restrict__ q, const float* __restrict__ k,
            const float* __restrict__ v, const float* __restrict__ relk,
            float* __restrict__ o, float* __restrict__ attn_out)
{
    __shared__ float sq[CHUNK_][129];
    __shared__ float sk[CTX_][129];
    __shared__ float sv[CTX_][129];
    __shared__ float sr[CTX_][129];
    __shared__ float sac[CHUNK_][CTX_];
    __shared__ float sbd[CHUNK_][CTX_];
    __shared__ float sw[CHUNK_][25];

    const int n = blockIdx.x, h = blockIdx.y, b = blockIdx.z;
    const int t = threadIdx.x;

    for (int i = t; i < CHUNK_ * D_; i += 384) {
        const int c = i >> 7, d = i & 127;
        const int s = n * CHUNK_ + c;
        sq[c][d] = q[((size_t)(b * S_ + s)) * E_ + h * D_ + d];
    }
    for (int i = t; i < CTX_ * D_; i += 384) {
        const int j = i >> 7, d = i & 127;
        const int s = n * CHUNK_ - 12 + j;
        float kv = 0.f, vv = 0.f;
        if (s >= 0 && s < S_) {
            const size_t base = ((size_t)(b * S_ + s)) * E_ + h * D_ + d;
            kv = k[base]; vv = v[base];
        }
        sk[j][d] = kv;
        sv[j][d] = vv;
        sr[j][d] = relk[(size_t)j * E_ + h * D_ + d];
    }
    __syncthreads();

    for (int i = t; i < CHUNK_ * CTX_; i += 384) {
        const int c = i / CTX_, j = i % CTX_;
        float a = 0.f, bb = 0.f;
#pragma unroll 8
        for (int d = 0; d < D_; d++) {
            const float qq = sq[c][d];
            a  = fmaf(qq, sk[j][d], a);
            bb = fmaf(qq, sr[j][d], bb);
        }
        sac[c][j] = a;
        sbd[c][j] = bb;
    }
    __syncthreads();

    for (int i = t; i < CHUNK_ * CTX_; i += 384) {
        const int c = i / CTX_, j = i % CTX_;
        const int idx = c * CTX_ + j;
        const int r = idx / (CTX_ + 1);
        const int p = idx % (CTX_ + 1);
        const float bd = (p < CTX_) ? sbd[r][p] : 0.f;
        float l = sac[c][j] + bd;
        l = 50.f * tanhf(l * 0.02f);
        sw[c][j] = l;
    }
    __syncthreads();

    if (t < CHUNK_) {
        const int c = t;
        float m = -1e30f;
        for (int j = 0; j < CTX_; j++) m = fmaxf(m, sw[c][j]);
        float sum = 0.f;
        for (int j = 0; j < CTX_; j++) { const float e = expf(sw[c][j] - m); sum += e; sw[c][j] = e; }
        const float inv = 1.f / sum;
        for (int j = 0; j < CTX_; j++) sw[c][j] *= inv;
    }
    __syncthreads();

    if (attn_out) {
        for (int i = t; i < CHUNK_ * CTX_; i += 384) {
            const int c = i / CTX_, j = i % CTX_;
            attn_out[((((size_t)b * H_ + h) * NB_ + n) * CHUNK_ + c) * CTX_ + j] = sw[c][j];
        }
    }

    for (int i = t; i < CHUNK_ * D_; i += 384) {
        const int c = i >> 7, d = i & 127;
        float acc = 0.f;
#pragma unroll
        for (int j = 0; j < CTX_; j++) acc = fmaf(sw[c][j], sv[j][d], acc);
        o[((size_t)(b * S_ + n * CHUNK_ + c)) * E_ + h * D_ + d] = acc;
    }
}

// ---------------- launch -----------------------------------------------------
extern "C" void kernel_launch(void* const* d_in, const int* in_sizes, int n_in,
                              void* d_out, int out_size)
{
    const float* hs   = (const float*)d_in[0];
    const float* pe   = (const float*)d_in[1];
    const float* w_q  = (const float*)d_in[2];
    const float* w_k  = (const float*)d_in[3];
    const float* w_v  = (const float*)d_in[4];
    const float* w_p  = (const float*)d_in[5];
    const float* w_r  = (const float*)d_in[6];
    const float* pds  = (const float*)d_in[7];
    float* out = (float*)d_out;

    float *q, *k, *v, *o, *rk, *qs;
    cudaGetSymbolAddress((void**)&q,  g_q);
    cudaGetSymbolAddress((void**)&k,  g_k);
    cudaGetSymbolAddress((void**)&v,  g_v);
    cudaGetSymbolAddress((void**)&o,  g_o);
    cudaGetSymbolAddress((void**)&rk, g_relk);
    cudaGetSymbolAddress((void**)&qs, g_qdscale);

    __nv_bfloat16 *hsh, *hsl, *och, *ocl, *wh, *wl, *peh, *pel;
    cudaGetSymbolAddress((void**)&hsh, g_hs_hi);
    cudaGetSymbolAddress((void**)&hsl, g_hs_lo);
    cudaGetSymbolAddress((void**)&och, g_oc_hi);
    cudaGetSymbolAddress((void**)&ocl, g_oc_lo);
    cudaGetSymbolAddress((void**)&wh,  g_w_hi);
    cudaGetSymbolAddress((void**)&wl,  g_w_lo);
    cudaGetSymbolAddress((void**)&peh, g_pe_hi);
    cudaGetSymbolAddress((void**)&pel, g_pe_lo);

    cudaFuncSetAttribute(gemm_bf16x3, cudaFuncAttributeMaxDynamicSharedMemorySize, SMEM_GEMM_);

    prep_scale_kernel<<<1, 128>>>(pds, qs);

    const int n4hs = (int)(OUT_MAIN / 4);
    split_kernel<<<(n4hs + 255) / 256, 256>>>(hs, hsh, hsl, n4hs, n4hs);
    const int n4w = WELEM_ / 4;
    split_kernel<<<(n4w + 255) / 256, 256>>>(w_q, wh + 0*(size_t)WELEM_, wl + 0*(size_t)WELEM_, n4w, n4w);
    split_kernel<<<(n4w + 255) / 256, 256>>>(w_k, wh + 1*(size_t)WELEM_, wl + 1*(size_t)WELEM_, n4w, n4w);
    split_kernel<<<(n4w + 255) / 256, 256>>>(w_v, wh + 2*(size_t)WELEM_, wl + 2*(size_t)WELEM_, n4w, n4w);
    split_kernel<<<(n4w + 255) / 256, 256>>>(w_p, wh + 3*(size_t)WELEM_, wl + 3*(size_t)WELEM_, n4w, n4w);
    split_kernel<<<(n4w + 255) / 256, 256>>>(w_r, wh + 4*(size_t)WELEM_, wl + 4*(size_t)WELEM_, n4w, n4w);
    const int n4pe_v = CTX_ * E_ / 4, n4pe_t = 128 * E_ / 4;
    split_kernel<<<(n4pe_t + 255) / 256, 256>>>(pe, peh, pel, n4pe_v, n4pe_t);

    const dim3 gBig(E_ / 128, MTOK_ / 128);   // (12, 192)
    gemm_bf16x3<<<gBig, 256, SMEM_GEMM_>>>(hsh, hsl, wh + 0*(size_t)WELEM_, wl + 0*(size_t)WELEM_,
                                           q, MTOK_, E_, E_, 1, qs, 1.f);
    gemm_bf16x3<<<gBig, 256, SMEM_GEMM_>>>(hsh, hsl, wh + 1*(size_t)WELEM_, wl + 1*(size_t)WELEM_,
                                           k, MTOK_, E_, E_, 2, nullptr, KSCALE);
    gemm_bf16x3<<<gBig, 256, SMEM_GEMM_>>>(hsh, hsl, wh + 2*(size_t)WELEM_, wl + 2*(size_t)WELEM_,
                                           v, MTOK_, E_, E_, 0, nullptr, 1.f);
    gemm_bf16x3<<<dim3(E_ / 128, 1), 256, SMEM_GEMM_>>>(peh, pel, wh + 4*(size_t)WELEM_, wl + 4*(size_t)WELEM_,
                                           rk, CTX_, E_, E_, 0, nullptr, 1.f);

    float* attn = ((size_t)out_size >= OUT_MAIN + ATTN_SZ) ? (out + OUT_MAIN) : nullptr;
    attn_kernel<<<dim3(NB_, H_, B_), 384>>>(q, k, v, rk, o, attn);

    split_kernel<<<(n4hs + 255) / 256, 256>>>(o, och, ocl, n4hs, n4hs);
    gemm_bf16x3<<<gBig, 256, SMEM_GEMM_>>>(och, ocl, wh + 3*(size_t)WELEM_, wl + 3*(size_t)WELEM_,
                                           out, MTOK_, E_, E_, 0, nullptr, 1.f);
}

// round 6
// speedup vs baseline: 3.0135x; 1.0556x over previous
#include <cuda_runtime.h>
#include <cuda_bf16.h>
#include <stdint.h>
#include <math.h>

// ---------------- problem constants ----------------
#define B_    8
#define S_    3072
#define H_    12
#define D_    128
#define E_    1536
#define NB_   256
#define CHUNK_ 12
#define CTX_  24
#define MTOK_ (B_*S_)         // 24576

#define OUT_MAIN  ((size_t)MTOK_ * E_)
#define ATTN_SZ   ((size_t)B_*H_*NB_*CHUNK_*CTX_)
#define WELEM_    (E_*E_)

#define QSCALE_BASE (0.088388347648318447f / 0.69314718055994531f)
#define KSCALE      (1.3132616875182228f  / 0.69314718055994531f)

// ---------------- scratch (device globals) ----------------
__device__ float g_q[OUT_MAIN];
__device__ float g_k[OUT_MAIN];
__device__ float g_v[OUT_MAIN];
__device__ float g_o[OUT_MAIN];
__device__ float g_relk[CTX_ * E_];
__device__ float g_qdscale[D_];

__device__ __nv_bfloat16 g_hs_hi[OUT_MAIN];
__device__ __nv_bfloat16 g_hs_lo[OUT_MAIN];
__device__ __nv_bfloat16 g_oc_hi[OUT_MAIN];
__device__ __nv_bfloat16 g_oc_lo[OUT_MAIN];
__device__ __nv_bfloat16 g_w_hi[5][WELEM_];
__device__ __nv_bfloat16 g_w_lo[5][WELEM_];
__device__ __nv_bfloat16 g_pe_hi[128 * E_];
__device__ __nv_bfloat16 g_pe_lo[128 * E_];

// ---------------- helpers ----------------
__device__ __forceinline__ void mma_bf16(float c[4], unsigned a0, unsigned a1,
                                         unsigned a2, unsigned a3,
                                         unsigned b0, unsigned b1){
    asm volatile(
        "mma.sync.aligned.m16n8k16.row.col.f32.bf16.bf16.f32 "
        "{%0,%1,%2,%3}, {%4,%5,%6,%7}, {%8,%9}, {%0,%1,%2,%3};"
        : "+f"(c[0]), "+f"(c[1]), "+f"(c[2]), "+f"(c[3])
        : "r"(a0), "r"(a1), "r"(a2), "r"(a3), "r"(b0), "r"(b1));
}
__device__ __forceinline__ void cpasync16(unsigned saddr, const void* gptr){
    asm volatile("cp.async.cg.shared.global [%0], [%1], 16;"
                 :: "r"(saddr), "l"(gptr) : "memory");
}
__device__ __forceinline__ void ldsm4(unsigned r[4], unsigned addr){
    asm volatile("ldmatrix.sync.aligned.m8n8.x4.shared.b16 {%0,%1,%2,%3}, [%4];"
                 : "=r"(r[0]), "=r"(r[1]), "=r"(r[2]), "=r"(r[3]) : "r"(addr));
}

// ---------------- fp32 -> bf16 hi/lo split ----------------
__global__ void split_kernel(const float* __restrict__ src,
                             __nv_bfloat16* __restrict__ hi,
                             __nv_bfloat16* __restrict__ lo,
                             int nvalid4, int ntotal4)
{
    int i = blockIdx.x * 256 + threadIdx.x;
    if (i >= ntotal4) return;
    float4 x = (i < nvalid4) ? ((const float4*)src)[i] : make_float4(0.f,0.f,0.f,0.f);
    __nv_bfloat16 h0 = __float2bfloat16_rn(x.x);
    __nv_bfloat16 h1 = __float2bfloat16_rn(x.y);
    __nv_bfloat16 h2 = __float2bfloat16_rn(x.z);
    __nv_bfloat16 h3 = __float2bfloat16_rn(x.w);
    __nv_bfloat162* hp = (__nv_bfloat162*)(hi + (size_t)i * 4);
    hp[0] = __nv_bfloat162(h0, h1);
    hp[1] = __nv_bfloat162(h2, h3);
    __nv_bfloat162* lp = (__nv_bfloat162*)(lo + (size_t)i * 4);
    lp[0] = __nv_bfloat162(__float2bfloat16_rn(x.x - __bfloat162float(h0)),
                           __float2bfloat16_rn(x.y - __bfloat162float(h1)));
    lp[1] = __nv_bfloat162(__float2bfloat16_rn(x.z - __bfloat162float(h2)),
                           __float2bfloat16_rn(x.w - __bfloat162float(h3)));
}

__global__ void prep_scale_kernel(const float* __restrict__ pds, float* __restrict__ out)
{
    int d = threadIdx.x;
    if (d < D_) {
        float x = pds[d];
        float sp = (x > 20.f) ? x : log1pf(expf(x));
        out[d] = QSCALE_BASE * sp;
    }
}

// ============================================================================
// bf16x3 tensor-core NT GEMM with ldmatrix fragments.
// C[M,N] = A[M,K]*B[N,K]^T, 128x128 CTA tile, BK=32 halves, 256 threads,
// warp tile 64x32, m16n8k16 bf16, 3 passes (Ah*Bh + Al*Bh + Ah*Bl).
// ============================================================================
#define BKH_   32                    // K halves per tile
#define LDAH_  40                    // 80B pitch -> conflict-free LDSM phases
#define TILEB_ (128*LDAH_*2)         // 10240 bytes per matrix tile
#define BUFB_  (4*TILEB_)            // Ah, Al, Bh, Bl
#define SMEM_GEMM_ (2*BUFB_)         // 81920

__global__ void __launch_bounds__(256, 2)
gemm_bf16x3(const __nv_bfloat16* __restrict__ Ahi, const __nv_bfloat16* __restrict__ Alo,
            const __nv_bfloat16* __restrict__ Bhi, const __nv_bfloat16* __restrict__ Blo,
            float* __restrict__ C, int M, int N, int K,
            int mode, const float* __restrict__ colscale, float cscale)
{
    extern __shared__ char smem[];
    const unsigned sb = (unsigned)__cvta_generic_to_shared(smem);

    const int bm = blockIdx.y * 128;
    const int bn = blockIdx.x * 128;
    const int tid  = threadIdx.x;
    const int lane = tid & 31;
    const int warp = tid >> 5;
    const int wm = warp >> 2;       // 0..1
    const int wn = warp & 3;        // 0..3
    const int lr = lane >> 2;       // 0..7
    const int lc = lane & 3;        // 0..3

    float acc[4][4][4];
#pragma unroll
    for (int i = 0; i < 4; i++)
#pragma unroll
        for (int j = 0; j < 4; j++)
#pragma unroll
            for (int r = 0; r < 4; r++) acc[i][j][r] = 0.f;

    const int NK = K / BKH_;        // 48

    // ---- per-thread ldmatrix base byte-offsets within a tile ----
    // x4 tile groups: g = lane>>3 (matrix index), tr = lane&7 (row in matrix)
    const int g  = lane >> 3;
    const int tr = lane & 7;
    // A (per mt): matrices M0..M3 = (r..r+7,k0..7),(r+8..,k0..7),(r..,k8..15),(r+8..,k8..15)
    unsigned aoff[4];
#pragma unroll
    for (int mt = 0; mt < 4; mt++) {
        const int row = wm * 64 + mt * 16 + (g & 1) * 8 + tr;
        const int col = (g >> 1) * 8;
        aoff[mt] = (unsigned)((row * LDAH_ + col) * 2);
    }
    // B (per nt-pair): M0,M1 = (n0..n0+7, k0..7),(n0..n0+7, k8..15); M2,M3 same +8n
    unsigned boff[2];
#pragma unroll
    for (int n2 = 0; n2 < 2; n2++) {
        const int n = wn * 32 + n2 * 16 + (g >> 1) * 8 + tr;
        const int col = (g & 1) * 8;
        boff[n2] = (unsigned)((n * LDAH_ + col) * 2);
    }

    // loader: tt selects matrix (Ah,Al,Bh,Bl); 8 x 16B chunks per thread
    const int tt  = tid >> 6;
    const int loc = tid & 63;
    const __nv_bfloat16* gbase =
        (tt == 0) ? Ahi : (tt == 1) ? Alo : (tt == 2) ? Bhi : Blo;
    const int rbase = (tt < 2) ? bm : bn;

    auto issue_loads = [&](int it, int buf){
        const int kt = it * BKH_;
#pragma unroll
        for (int i = 0; i < 8; i++) {
            const int cid = loc * 8 + i;       // 0..511
            const int row = cid >> 2;          // 0..127
            const int ch  = cid & 3;           // 0..3 (16B = 8 halves)
            const unsigned soff = (unsigned)(buf * BUFB_ + tt * TILEB_ + row * (LDAH_*2) + ch * 16);
            cpasync16(sb + soff, gbase + (size_t)(rbase + row) * K + kt + ch * 8);
        }
        asm volatile("cp.async.commit_group;" ::: "memory");
    };

    issue_loads(0, 0);
    int buf = 0;

    for (int it = 0; it < NK; it++) {
        if (it + 1 < NK) {
            issue_loads(it + 1, buf ^ 1);
            asm volatile("cp.async.wait_group 1;" ::: "memory");
        } else {
            asm volatile("cp.async.wait_group 0;" ::: "memory");
        }
        __syncthreads();

        const unsigned base = sb + buf * BUFB_;
        const unsigned sAh = base;
        const unsigned sAl = base + TILEB_;
        const unsigned sBh = base + 2 * TILEB_;
        const unsigned sBl = base + 3 * TILEB_;

#pragma unroll
        for (int k0 = 0; k0 < BKH_; k0 += 16) {
            const unsigned kb = (unsigned)(k0 * 2);

            // pass 1: Ah * Bh
            unsigned ah[4][4], bh[2][4];
#pragma unroll
            for (int mt = 0; mt < 4; mt++) ldsm4(ah[mt], sAh + aoff[mt] + kb);
#pragma unroll
            for (int n2 = 0; n2 < 2; n2++) ldsm4(bh[n2], sBh + boff[n2] + kb);
#pragma unroll
            for (int mt = 0; mt < 4; mt++)
#pragma unroll
                for (int nt = 0; nt < 4; nt++)
                    mma_bf16(acc[mt][nt], ah[mt][0], ah[mt][1], ah[mt][2], ah[mt][3],
                             bh[nt >> 1][(nt & 1) * 2], bh[nt >> 1][(nt & 1) * 2 + 1]);

            // pass 2: Al * Bh
            unsigned xl[4][4];
#pragma unroll
            for (int mt = 0; mt < 4; mt++) ldsm4(xl[mt], sAl + aoff[mt] + kb);
#pragma unroll
            for (int mt = 0; mt < 4; mt++)
#pragma unroll
                for (int nt = 0; nt < 4; nt++)
                    mma_bf16(acc[mt][nt], xl[mt][0], xl[mt][1], xl[mt][2], xl[mt][3],
                             bh[nt >> 1][(nt & 1) * 2], bh[nt >> 1][(nt & 1) * 2 + 1]);

            // pass 3: Ah * Bl (reuse xl storage for bl)
#pragma unroll
            for (int n2 = 0; n2 < 2; n2++) ldsm4(xl[n2], sBl + boff[n2] + kb);
#pragma unroll
            for (int mt = 0; mt < 4; mt++)
#pragma unroll
                for (int nt = 0; nt < 4; nt++)
                    mma_bf16(acc[mt][nt], ah[mt][0], ah[mt][1], ah[mt][2], ah[mt][3],
                             xl[nt >> 1][(nt & 1) * 2], xl[nt >> 1][(nt & 1) * 2 + 1]);
        }
        __syncthreads();
        buf ^= 1;
    }

    // --- epilogue ---
#pragma unroll
    for (int mt = 0; mt < 4; mt++) {
#pragma unroll
        for (int nt = 0; nt < 4; nt++) {
            const int r0 = bm + wm * 64 + mt * 16 + lr;
            const int c0 = bn + wn * 32 + nt * 8 + 2 * lc;
            float v0 = acc[mt][nt][0], v1 = acc[mt][nt][1];
            float v2 = acc[mt][nt][2], v3 = acc[mt][nt][3];
            if (mode == 1) {
                const float s0 = colscale[c0 & (D_-1)], s1 = colscale[(c0+1) & (D_-1)];
                v0 *= s0; v1 *= s1; v2 *= s0; v3 *= s1;
            } else if (mode == 2) {
                v0 *= cscale; v1 *= cscale; v2 *= cscale; v3 *= cscale;
            }
            if (r0 < M)     *(float2*)(C + (size_t)r0      * N + c0) = make_float2(v0, v1);
            if (r0 + 8 < M) *(float2*)(C + (size_t)(r0+8)  * N + c0) = make_float2(v2, v3);
        }
    }
}

// ---------------- chunked local attention -----------------------------------
__global__ void __launch_bounds__(384)
attn_kernel(const float* __restrict__ q, const float* __restrict__ k,
            const float* __restrict__ v, const float* __restrict__ relk,
            float* __restrict__ o, float* __restrict__ attn_out)
{
    __shared__ float sq[CHUNK_][129];
    __shared__ float sk[CTX_][129];
    __shared__ float sv[CTX_][129];
    __shared__ float sr[CTX_][129];
    __shared__ float sac[CHUNK_][CTX_];
    __shared__ float sbd[CHUNK_][CTX_];
    __shared__ float sw[CHUNK_][25];

    const int n = blockIdx.x, h = blockIdx.y, b = blockIdx.z;
    const int t = threadIdx.x;

    for (int i = t; i < CHUNK_ * D_; i += 384) {
        const int c = i >> 7, d = i & 127;
        const int s = n * CHUNK_ + c;
        sq[c][d] = q[((size_t)(b * S_ + s)) * E_ + h * D_ + d];
    }
    for (int i = t; i < CTX_ * D_; i += 384) {
        const int j = i >> 7, d = i & 127;
        const int s = n * CHUNK_ - 12 + j;
        float kv = 0.f, vv = 0.f;
        if (s >= 0 && s < S_) {
            const size_t base = ((size_t)(b * S_ + s)) * E_ + h * D_ + d;
            kv = k[base]; vv = v[base];
        }
        sk[j][d] = kv;
        sv[j][d] = vv;
        sr[j][d] = relk[(size_t)j * E_ + h * D_ + d];
    }
    __syncthreads();

    for (int i = t; i < CHUNK_ * CTX_; i += 384) {
        const int c = i / CTX_, j = i % CTX_;
        float a = 0.f, bb = 0.f;
#pragma unroll 8
        for (int d = 0; d < D_; d++) {
            const float qq = sq[c][d];
            a  = fmaf(qq, sk[j][d], a);
            bb = fmaf(qq, sr[j][d], bb);
        }
        sac[c][j] = a;
        sbd[c][j] = bb;
    }
    __syncthreads();

    for (int i = t; i < CHUNK_ * CTX_; i += 384) {
        const int c = i / CTX_, j = i % CTX_;
        const int idx = c * CTX_ + j;
        const int r = idx / (CTX_ + 1);
        const int p = idx % (CTX_ + 1);
        const float bd = (p < CTX_) ? sbd[r][p] : 0.f;
        float l = sac[c][j] + bd;
        l = 50.f * tanhf(l * 0.02f);
        sw[c][j] = l;
    }
    __syncthreads();

    if (t < CHUNK_) {
        const int c = t;
        float m = -1e30f;
        for (int j = 0; j < CTX_; j++) m = fmaxf(m, sw[c][j]);
        float sum = 0.f;
        for (int j = 0; j < CTX_; j++) { const float e = expf(sw[c][j] - m); sum += e; sw[c][j] = e; }
        const float inv = 1.f / sum;
        for (int j = 0; j < CTX_; j++) sw[c][j] *= inv;
    }
    __syncthreads();

    if (attn_out) {
        for (int i = t; i < CHUNK_ * CTX_; i += 384) {
            const int c = i / CTX_, j = i % CTX_;
            attn_out[((((size_t)b * H_ + h) * NB_ + n) * CHUNK_ + c) * CTX_ + j] = sw[c][j];
        }
    }

    for (int i = t; i < CHUNK_ * D_; i += 384) {
        const int c = i >> 7, d = i & 127;
        float acc = 0.f;
#pragma unroll
        for (int j = 0; j < CTX_; j++) acc = fmaf(sw[c][j], sv[j][d], acc);
        o[((size_t)(b * S_ + n * CHUNK_ + c)) * E_ + h * D_ + d] = acc;
    }
}

// ---------------- launch -----------------------------------------------------
extern "C" void kernel_launch(void* const* d_in, const int* in_sizes, int n_in,
                              void* d_out, int out_size)
{
    const float* hs   = (const float*)d_in[0];
    const float* pe   = (const float*)d_in[1];
    const float* w_q  = (const float*)d_in[2];
    const float* w_k  = (const float*)d_in[3];
    const float* w_v  = (const float*)d_in[4];
    const float* w_p  = (const float*)d_in[5];
    const float* w_r  = (const float*)d_in[6];
    const float* pds  = (const float*)d_in[7];
    float* out = (float*)d_out;

    float *q, *k, *v, *o, *rk, *qs;
    cudaGetSymbolAddress((void**)&q,  g_q);
    cudaGetSymbolAddress((void**)&k,  g_k);
    cudaGetSymbolAddress((void**)&v,  g_v);
    cudaGetSymbolAddress((void**)&o,  g_o);
    cudaGetSymbolAddress((void**)&rk, g_relk);
    cudaGetSymbolAddress((void**)&qs, g_qdscale);

    __nv_bfloat16 *hsh, *hsl, *och, *ocl, *wh, *wl, *peh, *pel;
    cudaGetSymbolAddress((void**)&hsh, g_hs_hi);
    cudaGetSymbolAddress((void**)&hsl, g_hs_lo);
    cudaGetSymbolAddress((void**)&och, g_oc_hi);
    cudaGetSymbolAddress((void**)&ocl, g_oc_lo);
    cudaGetSymbolAddress((void**)&wh,  g_w_hi);
    cudaGetSymbolAddress((void**)&wl,  g_w_lo);
    cudaGetSymbolAddress((void**)&peh, g_pe_hi);
    cudaGetSymbolAddress((void**)&pel, g_pe_lo);

    cudaFuncSetAttribute(gemm_bf16x3, cudaFuncAttributeMaxDynamicSharedMemorySize, SMEM_GEMM_);

    prep_scale_kernel<<<1, 128>>>(pds, qs);

    const int n4hs = (int)(OUT_MAIN / 4);
    split_kernel<<<(n4hs + 255) / 256, 256>>>(hs, hsh, hsl, n4hs, n4hs);
    const int n4w = WELEM_ / 4;
    split_kernel<<<(n4w + 255) / 256, 256>>>(w_q, wh + 0*(size_t)WELEM_, wl + 0*(size_t)WELEM_, n4w, n4w);
    split_kernel<<<(n4w + 255) / 256, 256>>>(w_k, wh + 1*(size_t)WELEM_, wl + 1*(size_t)WELEM_, n4w, n4w);
    split_kernel<<<(n4w + 255) / 256, 256>>>(w_v, wh + 2*(size_t)WELEM_, wl + 2*(size_t)WELEM_, n4w, n4w);
    split_kernel<<<(n4w + 255) / 256, 256>>>(w_p, wh + 3*(size_t)WELEM_, wl + 3*(size_t)WELEM_, n4w, n4w);
    split_kernel<<<(n4w + 255) / 256, 256>>>(w_r, wh + 4*(size_t)WELEM_, wl + 4*(size_t)WELEM_, n4w, n4w);
    const int n4pe_v = CTX_ * E_ / 4, n4pe_t = 128 * E_ / 4;
    split_kernel<<<(n4pe_t + 255) / 256, 256>>>(pe, peh, pel, n4pe_v, n4pe_t);

    const dim3 gBig(E_ / 128, MTOK_ / 128);   // (12, 192)
    gemm_bf16x3<<<gBig, 256, SMEM_GEMM_>>>(hsh, hsl, wh + 0*(size_t)WELEM_, wl + 0*(size_t)WELEM_,
                                           q, MTOK_, E_, E_, 1, qs, 1.f);
    gemm_bf16x3<<<gBig, 256, SMEM_GEMM_>>>(hsh, hsl, wh + 1*(size_t)WELEM_, wl + 1*(size_t)WELEM_,
                                           k, MTOK_, E_, E_, 2, nullptr, KSCALE);
    gemm_bf16x3<<<gBig, 256, SMEM_GEMM_>>>(hsh, hsl, wh + 2*(size_t)WELEM_, wl + 2*(size_t)WELEM_,
                                           v, MTOK_, E_, E_, 0, nullptr, 1.f);
    gemm_bf16x3<<<dim3(E_ / 128, 1), 256, SMEM_GEMM_>>>(peh, pel, wh + 4*(size_t)WELEM_, wl + 4*(size_t)WELEM_,
                                           rk, CTX_, E_, E_, 0, nullptr, 1.f);

    float* attn = ((size_t)out_size >= OUT_MAIN + ATTN_SZ) ? (out + OUT_MAIN) : nullptr;
    attn_kernel<<<dim3(NB_, H_, B_), 384>>>(q, k, v, rk, o, attn);

    split_kernel<<<(n4hs + 255) / 256, 256>>>(o, och, ocl, n4hs, n4hs);
    gemm_bf16x3<<<gBig, 256, SMEM_GEMM_>>>(och, ocl, wh + 3*(size_t)WELEM_, wl + 3*(size_t)WELEM_,
                                           out, MTOK_, E_, E_, 0, nullptr, 1.f);
}

// round 7
// speedup vs baseline: 3.0158x; 1.0008x over previous
#include <cuda_runtime.h>
#include <cuda_bf16.h>
#include <stdint.h>
#include <math.h>

// ---------------- problem constants ----------------
#define B_    8
#define S_    3072
#define H_    12
#define D_    128
#define E_    1536
#define NB_   256
#define CHUNK_ 12
#define CTX_  24
#define MTOK_ (B_*S_)         // 24576

#define OUT_MAIN  ((size_t)MTOK_ * E_)
#define ATTN_SZ   ((size_t)B_*H_*NB_*CHUNK_*CTX_)
#define WELEM_    (E_*E_)

#define QSCALE_BASE (0.088388347648318447f / 0.69314718055994531f)
#define KSCALE      (1.3132616875182228f  / 0.69314718055994531f)

// ---------------- scratch (device globals) ----------------
__device__ float g_q[OUT_MAIN];
__device__ float g_k[OUT_MAIN];
__device__ float g_v[OUT_MAIN];
__device__ float g_o[OUT_MAIN];
__device__ float g_relk[CTX_ * E_];
__device__ float g_qdscale[D_];

__device__ __nv_bfloat16 g_hs_hi[OUT_MAIN];
__device__ __nv_bfloat16 g_hs_lo[OUT_MAIN];
__device__ __nv_bfloat16 g_oc_hi[OUT_MAIN];
__device__ __nv_bfloat16 g_oc_lo[OUT_MAIN];
__device__ __nv_bfloat16 g_w_hi[5][WELEM_];
__device__ __nv_bfloat16 g_w_lo[5][WELEM_];
__device__ __nv_bfloat16 g_pe_hi[256 * E_];
__device__ __nv_bfloat16 g_pe_lo[256 * E_];

// ---------------- helpers ----------------
__device__ __forceinline__ void mma_bf16(float c[4], unsigned a0, unsigned a1,
                                         unsigned a2, unsigned a3,
                                         unsigned b0, unsigned b1){
    asm volatile(
        "mma.sync.aligned.m16n8k16.row.col.f32.bf16.bf16.f32 "
        "{%0,%1,%2,%3}, {%4,%5,%6,%7}, {%8,%9}, {%0,%1,%2,%3};"
        : "+f"(c[0]), "+f"(c[1]), "+f"(c[2]), "+f"(c[3])
        : "r"(a0), "r"(a1), "r"(a2), "r"(a3), "r"(b0), "r"(b1));
}
__device__ __forceinline__ void cpasync16(unsigned saddr, const void* gptr){
    asm volatile("cp.async.cg.shared.global [%0], [%1], 16;"
                 :: "r"(saddr), "l"(gptr) : "memory");
}
__device__ __forceinline__ void cpasync16z(unsigned saddr, const void* gptr, int sz){
    asm volatile("cp.async.cg.shared.global [%0], [%1], 16, %2;"
                 :: "r"(saddr), "l"(gptr), "r"(sz) : "memory");
}
__device__ __forceinline__ void ldsm4(unsigned r[4], unsigned addr){
    asm volatile("ldmatrix.sync.aligned.m8n8.x4.shared.b16 {%0,%1,%2,%3}, [%4];"
                 : "=r"(r[0]), "=r"(r[1]), "=r"(r[2]), "=r"(r[3]) : "r"(addr));
}

// ---------------- fp32 -> bf16 hi/lo split ----------------
__global__ void split_kernel(const float* __restrict__ src,
                             __nv_bfloat16* __restrict__ hi,
                             __nv_bfloat16* __restrict__ lo,
                             int nvalid4, int ntotal4)
{
    int i = blockIdx.x * 256 + threadIdx.x;
    if (i >= ntotal4) return;
    float4 x = (i < nvalid4) ? ((const float4*)src)[i] : make_float4(0.f,0.f,0.f,0.f);
    __nv_bfloat16 h0 = __float2bfloat16_rn(x.x);
    __nv_bfloat16 h1 = __float2bfloat16_rn(x.y);
    __nv_bfloat16 h2 = __float2bfloat16_rn(x.z);
    __nv_bfloat16 h3 = __float2bfloat16_rn(x.w);
    __nv_bfloat162* hp = (__nv_bfloat162*)(hi + (size_t)i * 4);
    hp[0] = __nv_bfloat162(h0, h1);
    hp[1] = __nv_bfloat162(h2, h3);
    __nv_bfloat162* lp = (__nv_bfloat162*)(lo + (size_t)i * 4);
    lp[0] = __nv_bfloat162(__float2bfloat16_rn(x.x - __bfloat162float(h0)),
                           __float2bfloat16_rn(x.y - __bfloat162float(h1)));
    lp[1] = __nv_bfloat162(__float2bfloat16_rn(x.z - __bfloat162float(h2)),
                           __float2bfloat16_rn(x.w - __bfloat162float(h3)));
}

__global__ void prep_scale_kernel(const float* __restrict__ pds, float* __restrict__ out)
{
    int d = threadIdx.x;
    if (d < D_) {
        float x = pds[d];
        float sp = (x > 20.f) ? x : log1pf(expf(x));
        out[d] = QSCALE_BASE * sp;
    }
}

// ============================================================================
// bf16x3 tensor-core NT GEMM, 256x128 CTA tile, 512 threads, 3-stage pipeline.
// C[M,N] = A[M,K]*B[N,K]^T; warp tile 64x32 (4x4 warps); m16n8k16 bf16;
// 3 passes: Ah*Bh + Al*Bh + Ah*Bl.
// ============================================================================
#define BKH_   32                     // K halves per stage
#define LDAH_  40                     // 80B pitch (64B data + 16B pad)
#define AROWS_ 256
#define BROWS_ 128
#define STAGEB_ ((2*AROWS_ + 2*BROWS_) * LDAH_ * 2)   // 61440 bytes
#define NSTAGE_ 3
#define SMEM_GEMM_ (NSTAGE_ * STAGEB_)                // 184320

#define OFF_AH_ 0
#define OFF_AL_ (AROWS_ * LDAH_ * 2)
#define OFF_BH_ (2 * AROWS_ * LDAH_ * 2)
#define OFF_BL_ ((2 * AROWS_ + BROWS_) * LDAH_ * 2)

__global__ void __launch_bounds__(512, 1)
gemm_bf16x3(const __nv_bfloat16* __restrict__ Ahi, const __nv_bfloat16* __restrict__ Alo,
            const __nv_bfloat16* __restrict__ Bhi, const __nv_bfloat16* __restrict__ Blo,
            float* __restrict__ C, int M, int N, int K,
            int mode, const float* __restrict__ colscale, float cscale)
{
    extern __shared__ char smem[];
    const unsigned sb = (unsigned)__cvta_generic_to_shared(smem);

    const int bm = blockIdx.y * 256;
    const int bn = blockIdx.x * 128;
    const int tid  = threadIdx.x;
    const int lane = tid & 31;
    const int warp = tid >> 5;
    const int wm = warp >> 2;       // 0..3
    const int wn = warp & 3;        // 0..3
    const int lr = lane >> 2;
    const int lc = lane & 3;

    float acc[4][4][4];
#pragma unroll
    for (int i = 0; i < 4; i++)
#pragma unroll
        for (int j = 0; j < 4; j++)
#pragma unroll
            for (int r = 0; r < 4; r++) acc[i][j][r] = 0.f;

    const int NK = K / BKH_;        // 48

    // ---- ldmatrix per-thread base offsets ----
    const int g  = lane >> 3;
    const int tr = lane & 7;
    unsigned aoff[4];
#pragma unroll
    for (int mt = 0; mt < 4; mt++) {
        const int row = wm * 64 + mt * 16 + (g & 1) * 8 + tr;
        const int col = (g >> 1) * 8;
        aoff[mt] = (unsigned)((row * LDAH_ + col) * 2);
    }
    unsigned boff[2];
#pragma unroll
    for (int n2 = 0; n2 < 2; n2++) {
        const int n = wn * 32 + n2 * 16 + (g >> 1) * 8 + tr;
        const int col = (g & 1) * 8;
        boff[n2] = (unsigned)((n * LDAH_ + col) * 2);
    }

    // ---- loader: 6 x 16B chunks per thread (3072 chunks total) ----
    auto issue_loads = [&](int it, int stage){
        const int kt = it * BKH_;
        const unsigned sbase = sb + stage * STAGEB_;
#pragma unroll
        for (int i = 0; i < 6; i++) {
            const int cid  = tid * 6 + i;        // 0..3071
            const int row  = cid >> 2;           // 0..767
            const int ch   = cid & 3;            // 16B chunk within 64B data
            const unsigned soff = (unsigned)(row * (LDAH_ * 2) + ch * 16);
            if (row < 2 * AROWS_) {
                const int ar = row & (AROWS_ - 1);
                const __nv_bfloat16* src = (row < AROWS_) ? Ahi : Alo;
                const int gr = bm + ar;
                const int sz = (gr < M) ? 16 : 0;
                const int grc = (gr < M) ? gr : 0;
                cpasync16z(sbase + soff, src + (size_t)grc * K + kt + ch * 8, sz);
            } else {
                const int br = (row - 2 * AROWS_) & (BROWS_ - 1);
                const __nv_bfloat16* src = (row < 2 * AROWS_ + BROWS_) ? Bhi : Blo;
                cpasync16(sbase + soff, src + (size_t)(bn + br) * K + kt + ch * 8);
            }
        }
        asm volatile("cp.async.commit_group;" ::: "memory");
    };

    issue_loads(0, 0);
    issue_loads(1, 1);

    int stage = 0;
    for (int it = 0; it < NK; it++) {
        if (it < NK - 1) asm volatile("cp.async.wait_group 1;" ::: "memory");
        else             asm volatile("cp.async.wait_group 0;" ::: "memory");
        __syncthreads();
        if (it + 2 < NK) {
            int ws = stage + 2; if (ws >= NSTAGE_) ws -= NSTAGE_;
            issue_loads(it + 2, ws);
        }

        const unsigned base = sb + stage * STAGEB_;
        const unsigned sAh = base + OFF_AH_;
        const unsigned sAl = base + OFF_AL_;
        const unsigned sBh = base + OFF_BH_;
        const unsigned sBl = base + OFF_BL_;

#pragma unroll
        for (int k0 = 0; k0 < BKH_; k0 += 16) {
            const unsigned kb = (unsigned)(k0 * 2);

            unsigned ah[4][4], bh[2][4];
#pragma unroll
            for (int mt = 0; mt < 4; mt++) ldsm4(ah[mt], sAh + aoff[mt] + kb);
#pragma unroll
            for (int n2 = 0; n2 < 2; n2++) ldsm4(bh[n2], sBh + boff[n2] + kb);
#pragma unroll
            for (int mt = 0; mt < 4; mt++)
#pragma unroll
                for (int nt = 0; nt < 4; nt++)
                    mma_bf16(acc[mt][nt], ah[mt][0], ah[mt][1], ah[mt][2], ah[mt][3],
                             bh[nt >> 1][(nt & 1) * 2], bh[nt >> 1][(nt & 1) * 2 + 1]);

            unsigned xl[4][4];
#pragma unroll
            for (int mt = 0; mt < 4; mt++) ldsm4(xl[mt], sAl + aoff[mt] + kb);
#pragma unroll
            for (int mt = 0; mt < 4; mt++)
#pragma unroll
                for (int nt = 0; nt < 4; nt++)
                    mma_bf16(acc[mt][nt], xl[mt][0], xl[mt][1], xl[mt][2], xl[mt][3],
                             bh[nt >> 1][(nt & 1) * 2], bh[nt >> 1][(nt & 1) * 2 + 1]);

#pragma unroll
            for (int n2 = 0; n2 < 2; n2++) ldsm4(xl[n2], sBl + boff[n2] + kb);
#pragma unroll
            for (int mt = 0; mt < 4; mt++)
#pragma unroll
                for (int nt = 0; nt < 4; nt++)
                    mma_bf16(acc[mt][nt], ah[mt][0], ah[mt][1], ah[mt][2], ah[mt][3],
                             xl[nt >> 1][(nt & 1) * 2], xl[nt >> 1][(nt & 1) * 2 + 1]);
        }
        stage++; if (stage >= NSTAGE_) stage = 0;
        __syncthreads();
    }

    // --- epilogue ---
#pragma unroll
    for (int mt = 0; mt < 4; mt++) {
#pragma unroll
        for (int nt = 0; nt < 4; nt++) {
            const int r0 = bm + wm * 64 + mt * 16 + lr;
            const int c0 = bn + wn * 32 + nt * 8 + 2 * lc;
            float v0 = acc[mt][nt][0], v1 = acc[mt][nt][1];
            float v2 = acc[mt][nt][2], v3 = acc[mt][nt][3];
            if (mode == 1) {
                const float s0 = colscale[c0 & (D_-1)], s1 = colscale[(c0+1) & (D_-1)];
                v0 *= s0; v1 *= s1; v2 *= s0; v3 *= s1;
            } else if (mode == 2) {
                v0 *= cscale; v1 *= cscale; v2 *= cscale; v3 *= cscale;
            }
            if (r0 < M)     *(float2*)(C + (size_t)r0      * N + c0) = make_float2(v0, v1);
            if (r0 + 8 < M) *(float2*)(C + (size_t)(r0+8)  * N + c0) = make_float2(v2, v3);
        }
    }
}

// ---------------- chunked local attention -----------------------------------
__global__ void __launch_bounds__(384)
attn_kernel(const float* __restrict__ q, const float* __restrict__ k,
            const float* __restrict__ v, const float* __restrict__ relk,
            float* __restrict__ o, float* __restrict__ attn_out)
{
    __shared__ float sq[CHUNK_][129];
    __shared__ float sk[CTX_][129];
    __shared__ float sv[CTX_][129];
    __shared__ float sr[CTX_][129];
    __shared__ float sac[CHUNK_][CTX_];
    __shared__ float sbd[CHUNK_][CTX_];
    __shared__ float sw[CHUNK_][25];

    const int n = blockIdx.x, h = blockIdx.y, b = blockIdx.z;
    const int t = threadIdx.x;

    for (int i = t; i < CHUNK_ * D_; i += 384) {
        const int c = i >> 7, d = i & 127;
        const int s = n * CHUNK_ + c;
        sq[c][d] = q[((size_t)(b * S_ + s)) * E_ + h * D_ + d];
    }
    for (int i = t; i < CTX_ * D_; i += 384) {
        const int j = i >> 7, d = i & 127;
        const int s = n * CHUNK_ - 12 + j;
        float kv = 0.f, vv = 0.f;
        if (s >= 0 && s < S_) {
            const size_t base = ((size_t)(b * S_ + s)) * E_ + h * D_ + d;
            kv = k[base]; vv = v[base];
        }
        sk[j][d] = kv;
        sv[j][d] = vv;
        sr[j][d] = relk[(size_t)j * E_ + h * D_ + d];
    }
    __syncthreads();

    for (int i = t; i < CHUNK_ * CTX_; i += 384) {
        const int c = i / CTX_, j = i % CTX_;
        float a = 0.f, bb = 0.f;
#pragma unroll 8
        for (int d = 0; d < D_; d++) {
            const float qq = sq[c][d];
            a  = fmaf(qq, sk[j][d], a);
            bb = fmaf(qq, sr[j][d], bb);
        }
        sac[c][j] = a;
        sbd[c][j] = bb;
    }
    __syncthreads();

    for (int i = t; i < CHUNK_ * CTX_; i += 384) {
        const int c = i / CTX_, j = i % CTX_;
        const int idx = c * CTX_ + j;
        const int r = idx / (CTX_ + 1);
        const int p = idx % (CTX_ + 1);
        const float bd = (p < CTX_) ? sbd[r][p] : 0.f;
        float l = sac[c][j] + bd;
        l = 50.f * tanhf(l * 0.02f);
        sw[c][j] = l;
    }
    __syncthreads();

    if (t < CHUNK_) {
        const int c = t;
        float m = -1e30f;
        for (int j = 0; j < CTX_; j++) m = fmaxf(m, sw[c][j]);
        float sum = 0.f;
        for (int j = 0; j < CTX_; j++) { const float e = expf(sw[c][j] - m); sum += e; sw[c][j] = e; }
        const float inv = 1.f / sum;
        for (int j = 0; j < CTX_; j++) sw[c][j] *= inv;
    }
    __syncthreads();

    if (attn_out) {
        for (int i = t; i < CHUNK_ * CTX_; i += 384) {
            const int c = i / CTX_, j = i % CTX_;
            attn_out[((((size_t)b * H_ + h) * NB_ + n) * CHUNK_ + c) * CTX_ + j] = sw[c][j];
        }
    }

    for (int i = t; i < CHUNK_ * D_; i += 384) {
        const int c = i >> 7, d = i & 127;
        float acc = 0.f;
#pragma unroll
        for (int j = 0; j < CTX_; j++) acc = fmaf(sw[c][j], sv[j][d], acc);
        o[((size_t)(b * S_ + n * CHUNK_ + c)) * E_ + h * D_ + d] = acc;
    }
}

// ---------------- launch -----------------------------------------------------
extern "C" void kernel_launch(void* const* d_in, const int* in_sizes, int n_in,
                              void* d_out, int out_size)
{
    const float* hs   = (const float*)d_in[0];
    const float* pe   = (const float*)d_in[1];
    const float* w_q  = (const float*)d_in[2];
    const float* w_k  = (const float*)d_in[3];
    const float* w_v  = (const float*)d_in[4];
    const float* w_p  = (const float*)d_in[5];
    const float* w_r  = (const float*)d_in[6];
    const float* pds  = (const float*)d_in[7];
    float* out = (float*)d_out;

    float *q, *k, *v, *o, *rk, *qs;
    cudaGetSymbolAddress((void**)&q,  g_q);
    cudaGetSymbolAddress((void**)&k,  g_k);
    cudaGetSymbolAddress((void**)&v,  g_v);
    cudaGetSymbolAddress((void**)&o,  g_o);
    cudaGetSymbolAddress((void**)&rk, g_relk);
    cudaGetSymbolAddress((void**)&qs, g_qdscale);

    __nv_bfloat16 *hsh, *hsl, *och, *ocl, *wh, *wl, *peh, *pel;
    cudaGetSymbolAddress((void**)&hsh, g_hs_hi);
    cudaGetSymbolAddress((void**)&hsl, g_hs_lo);
    cudaGetSymbolAddress((void**)&och, g_oc_hi);
    cudaGetSymbolAddress((void**)&ocl, g_oc_lo);
    cudaGetSymbolAddress((void**)&wh,  g_w_hi);
    cudaGetSymbolAddress((void**)&wl,  g_w_lo);
    cudaGetSymbolAddress((void**)&peh, g_pe_hi);
    cudaGetSymbolAddress((void**)&pel, g_pe_lo);

    cudaFuncSetAttribute(gemm_bf16x3, cudaFuncAttributeMaxDynamicSharedMemorySize, SMEM_GEMM_);

    prep_scale_kernel<<<1, 128>>>(pds, qs);

    const int n4hs = (int)(OUT_MAIN / 4);
    split_kernel<<<(n4hs + 255) / 256, 256>>>(hs, hsh, hsl, n4hs, n4hs);
    const int n4w = WELEM_ / 4;
    split_kernel<<<(n4w + 255) / 256, 256>>>(w_q, wh + 0*(size_t)WELEM_, wl + 0*(size_t)WELEM_, n4w, n4w);
    split_kernel<<<(n4w + 255) / 256, 256>>>(w_k, wh + 1*(size_t)WELEM_, wl + 1*(size_t)WELEM_, n4w, n4w);
    split_kernel<<<(n4w + 255) / 256, 256>>>(w_v, wh + 2*(size_t)WELEM_, wl + 2*(size_t)WELEM_, n4w, n4w);
    split_kernel<<<(n4w + 255) / 256, 256>>>(w_p, wh + 3*(size_t)WELEM_, wl + 3*(size_t)WELEM_, n4w, n4w);
    split_kernel<<<(n4w + 255) / 256, 256>>>(w_r, wh + 4*(size_t)WELEM_, wl + 4*(size_t)WELEM_, n4w, n4w);
    const int n4pe_v = CTX_ * E_ / 4, n4pe_t = 256 * E_ / 4;
    split_kernel<<<(n4pe_t + 255) / 256, 256>>>(pe, peh, pel, n4pe_v, n4pe_t);

    const dim3 gBig(E_ / 128, MTOK_ / 256);   // (12, 96)
    gemm_bf16x3<<<gBig, 512, SMEM_GEMM_>>>(hsh, hsl, wh + 0*(size_t)WELEM_, wl + 0*(size_t)WELEM_,
                                           q, MTOK_, E_, E_, 1, qs, 1.f);
    gemm_bf16x3<<<gBig, 512, SMEM_GEMM_>>>(hsh, hsl, wh + 1*(size_t)WELEM_, wl + 1*(size_t)WELEM_,
                                           k, MTOK_, E_, E_, 2, nullptr, KSCALE);
    gemm_bf16x3<<<gBig, 512, SMEM_GEMM_>>>(hsh, hsl, wh + 2*(size_t)WELEM_, wl + 2*(size_t)WELEM_,
                                           v, MTOK_, E_, E_, 0, nullptr, 1.f);
    gemm_bf16x3<<<dim3(E_ / 128, 1), 512, SMEM_GEMM_>>>(peh, pel, wh + 4*(size_t)WELEM_, wl + 4*(size_t)WELEM_,
                                           rk, CTX_, E_, E_, 0, nullptr, 1.f);

    float* attn = ((size_t)out_size >= OUT_MAIN + ATTN_SZ) ? (out + OUT_MAIN) : nullptr;
    attn_kernel<<<dim3(NB_, H_, B_), 384>>>(q, k, v, rk, o, attn);

    split_kernel<<<(n4hs + 255) / 256, 256>>>(o, och, ocl, n4hs, n4hs);
    gemm_bf16x3<<<gBig, 512, SMEM_GEMM_>>>(och, ocl, wh + 3*(size_t)WELEM_, wl + 3*(size_t)WELEM_,
                                           out, MTOK_, E_, E_, 0, nullptr, 1.f);
}